// round 1
// baseline (speedup 1.0000x reference)
#include <cuda_runtime.h>
#include <math.h>

// ---------------------------------------------------------------------------
// Problem: 64 images of 100x100. 2x2 patches (50x50 = 2500 per image).
// Per patch: 4-qubit statevector sim:
//   init: RY(pixel)|0> per qubit  (real product state)
//   ops : rx(p0)q0, ry(p1)q1, rz(p2)q2, CNOT(0,1), rx(p3)q3, CNOT(2,3),
//         ry(p4)q0, rz(p5)q1
//   meas: <Z_q> for q=0..3  -> feature idx = patch*4+q
// logits[b,k] = sum_f feats[b,f]*W[k,f] + bias[k];  out = log_softmax(logits)
// ---------------------------------------------------------------------------

#define NPS    50      // patches per side
#define SLICES 10
#define PPS    250     // patches per slice (2500/10)

__device__ float g_partial[64 * SLICES * 2];

// qubit w -> amplitude-index bit mask (q0 is MSB of 4-bit index)
// mask = 8 >> w

__device__ __forceinline__ void rx_g(float2 st[16], int m, float c, float s) {
#pragma unroll
    for (int k = 0; k < 16; k++) {
        if (k & m) continue;
        float2 a = st[k], b = st[k | m];
        // a' = c*a - i*s*b ; b' = -i*s*a + c*b
        st[k]     = make_float2(fmaf(c, a.x,  s * b.y), fmaf(c, a.y, -s * b.x));
        st[k | m] = make_float2(fmaf(s, a.y,  c * b.x), fmaf(-s, a.x, c * b.y));
    }
}

__device__ __forceinline__ void ry_g(float2 st[16], int m, float c, float s) {
#pragma unroll
    for (int k = 0; k < 16; k++) {
        if (k & m) continue;
        float2 a = st[k], b = st[k | m];
        st[k]     = make_float2(fmaf(c, a.x, -s * b.x), fmaf(c, a.y, -s * b.y));
        st[k | m] = make_float2(fmaf(s, a.x,  c * b.x), fmaf(s, a.y,  c * b.y));
    }
}

__device__ __forceinline__ void rz_g(float2 st[16], int m, float c, float s) {
#pragma unroll
    for (int k = 0; k < 16; k++) {
        float2 a = st[k];
        if (k & m)  // * (c + i s)
            st[k] = make_float2(fmaf(a.x, c, -a.y * s), fmaf(a.y, c,  a.x * s));
        else        // * (c - i s)
            st[k] = make_float2(fmaf(a.x, c,  a.y * s), fmaf(a.y, c, -a.x * s));
    }
}

__device__ __forceinline__ void cnot_g(float2 st[16], int mc, int mt) {
#pragma unroll
    for (int k = 0; k < 16; k++) {
        if ((k & mc) && !(k & mt)) {
            float2 t = st[k];
            st[k] = st[k | mt];
            st[k | mt] = t;
        }
    }
}

__global__ __launch_bounds__(256) void quanv_kernel(
    const float* __restrict__ x,
    const float* __restrict__ W,
    const float* __restrict__ qp)
{
    __shared__ float gc[6], gs[6];  // cos/sin of q_params/2 (precise)
    int tid = threadIdx.x;
    if (tid < 6) sincosf(0.5f * qp[tid], &gs[tid], &gc[tid]);
    __syncthreads();

    const int b     = blockIdx.x;
    const int slice = blockIdx.y;

    float acc0 = 0.f, acc1 = 0.f;

    if (tid < PPS) {
        const int pidx = slice * PPS + tid;
        const int i = pidx / NPS;
        const int j = pidx - i * NPS;

        const float* xb = x + b * 10000 + (2 * i) * 100 + 2 * j;
        float t0 = xb[0], t1 = xb[1], t2 = xb[100], t3 = xb[101];

        float c0, s0, c1, s1, c2, s2, c3, s3;
        __sincosf(0.5f * t0, &s0, &c0);
        __sincosf(0.5f * t1, &s1, &c1);
        __sincosf(0.5f * t2, &s2, &c2);
        __sincosf(0.5f * t3, &s3, &c3);

        float2 st[16];
#pragma unroll
        for (int k = 0; k < 16; k++) {
            float v = (k & 8 ? s0 : c0) * (k & 4 ? s1 : c1) *
                      (k & 2 ? s2 : c2) * (k & 1 ? s3 : c3);
            st[k] = make_float2(v, 0.f);
        }

        rx_g(st, 8, gc[0], gs[0]);   // rx(p0) on q0
        ry_g(st, 4, gc[1], gs[1]);   // ry(p1) on q1
        rz_g(st, 2, gc[2], gs[2]);   // rz(p2) on q2
        cnot_g(st, 8, 4);            // CNOT(0,1)
        rx_g(st, 1, gc[3], gs[3]);   // rx(p3) on q3
        cnot_g(st, 2, 1);            // CNOT(2,3)
        ry_g(st, 8, gc[4], gs[4]);   // ry(p4) on q0
        rz_g(st, 4, gc[5], gs[5]);   // rz(p5) on q1

        float m0 = 0.f, m1 = 0.f, m2 = 0.f, m3 = 0.f;
#pragma unroll
        for (int k = 0; k < 16; k++) {
            float p = fmaf(st[k].x, st[k].x, st[k].y * st[k].y);
            m0 += (k & 8) ? -p : p;
            m1 += (k & 4) ? -p : p;
            m2 += (k & 2) ? -p : p;
            m3 += (k & 1) ? -p : p;
        }

        const float4 w0 = *reinterpret_cast<const float4*>(W + pidx * 4);
        const float4 w1 = *reinterpret_cast<const float4*>(W + 10000 + pidx * 4);
        acc0 = fmaf(m0, w0.x, fmaf(m1, w0.y, fmaf(m2, w0.z, m3 * w0.w)));
        acc1 = fmaf(m0, w1.x, fmaf(m1, w1.y, fmaf(m2, w1.z, m3 * w1.w)));
    }

    // deterministic block reduction
    __shared__ float2 red[256];
    red[tid] = make_float2(acc0, acc1);
    __syncthreads();
#pragma unroll
    for (int s = 128; s > 0; s >>= 1) {
        if (tid < s) {
            red[tid].x += red[tid + s].x;
            red[tid].y += red[tid + s].y;
        }
        __syncthreads();
    }
    if (tid == 0) {
        g_partial[(b * SLICES + slice) * 2 + 0] = red[0].x;
        g_partial[(b * SLICES + slice) * 2 + 1] = red[0].y;
    }
}

__global__ void finalize_kernel(const float* __restrict__ bias,
                                float* __restrict__ out)
{
    int b = threadIdx.x;
    if (b >= 64) return;
    float l0 = bias[0], l1 = bias[1];
#pragma unroll
    for (int s = 0; s < SLICES; s++) {
        l0 += g_partial[(b * SLICES + s) * 2 + 0];
        l1 += g_partial[(b * SLICES + s) * 2 + 1];
    }
    float m = fmaxf(l0, l1);
    float lse = m + logf(expf(l0 - m) + expf(l1 - m));
    out[b * 2 + 0] = l0 - lse;
    out[b * 2 + 1] = l1 - lse;
}

extern "C" void kernel_launch(void* const* d_in, const int* in_sizes, int n_in,
                              void* d_out, int out_size)
{
    (void)in_sizes; (void)n_in; (void)out_size;
    const float* x    = (const float*)d_in[0];  // [64,100,100]
    const float* W    = (const float*)d_in[1];  // [2,10000]
    const float* bias = (const float*)d_in[2];  // [2]
    const float* qp   = (const float*)d_in[3];  // [6]

    dim3 grid(64, SLICES);
    quanv_kernel<<<grid, 256>>>(x, W, qp);
    finalize_kernel<<<1, 64>>>(bias, (float*)d_out);
}

// round 2
// speedup vs baseline: 1.5926x; 1.5926x over previous
#include <cuda_runtime.h>
#include <math.h>

// Closed-form collapse of the 4-qubit circuit (pairs (0,1) and (2,3) never
// couple; trailing RZ gates don't affect Z-basis probabilities):
//   m0 = cos(p4)cos(p0)cos(t0) - sin(p4)sin(t1+p1)sin(t0)
//   m1 = cos(t1+p1)cos(p0)cos(t0)
//   m2 = cos(t2)
//   m3 = cos(p3)cos(t2)cos(t3)
// where (t0,t1,t2,t3) = (x[2i,2j], x[2i,2j+1], x[2i+1,2j], x[2i+1,2j+1]).
// Then logits[b,k] = sum_patch m.W + bias; out = log_softmax.

#define BLK 640          // 20 warps
#define PAIRS 1250       // 2500 patches / 2 (two adjacent patches per thread)

__global__ __launch_bounds__(BLK) void fused_kernel(
    const float* __restrict__ x,
    const float* __restrict__ W,
    const float* __restrict__ bias,
    const float* __restrict__ qp,
    float* __restrict__ out)
{
    __shared__ float sK[5];
    __shared__ float2 warpred[BLK / 32];

    const int tid = threadIdx.x;
    if (tid == 0) {
        float p0 = qp[0], p1 = qp[1], p3 = qp[3], p4 = qp[4];
        float cp0 = cosf(p0), cp3 = cosf(p3);
        float sp4, cp4;
        sincosf(p4, &sp4, &cp4);
        sK[0] = cp4 * cp0;  // K1
        sK[1] = sp4;        // K2
        sK[2] = cp0;        // K3
        sK[3] = cp3;        // K4
        sK[4] = p1;
    }
    __syncthreads();
    const float K1 = sK[0], K2 = sK[1], K3 = sK[2], K4 = sK[3], P1 = sK[4];

    const int b = blockIdx.x;
    const float* xb = x + b * 10000;

    float acc0 = 0.f, acc1 = 0.f;

#pragma unroll
    for (int it = 0; it < 2; it++) {
        const int q = tid + it * BLK;       // pair index 0..1249
        if (q < PAIRS) {
            const int i  = q / 25;          // patch row 0..49
            const int jp = q - i * 25;      // pair column 0..24
            const float4 r0 = *reinterpret_cast<const float4*>(xb + 200 * i + 4 * jp);
            const float4 r1 = *reinterpret_cast<const float4*>(xb + 200 * i + 100 + 4 * jp);
            const int pidx = i * 50 + 2 * jp;
            const float4 wA0 = *reinterpret_cast<const float4*>(W + pidx * 4);
            const float4 wB0 = *reinterpret_cast<const float4*>(W + pidx * 4 + 4);
            const float4 wA1 = *reinterpret_cast<const float4*>(W + 10000 + pidx * 4);
            const float4 wB1 = *reinterpret_cast<const float4*>(W + 10000 + pidx * 4 + 4);

            // ---- patch A: t = (r0.x, r0.y, r1.x, r1.y)
            {
                float s0, c0, sa, ca;
                __sincosf(r0.x, &s0, &c0);
                __sincosf(r0.y + P1, &sa, &ca);
                const float ct2 = __cosf(r1.x);
                const float ct3 = __cosf(r1.y);
                const float m0 = fmaf(K1, c0, -K2 * sa * s0);
                const float m1 = K3 * ca * c0;
                const float m2 = ct2;
                const float m3 = K4 * ct2 * ct3;
                acc0 = fmaf(m0, wA0.x, fmaf(m1, wA0.y, fmaf(m2, wA0.z, fmaf(m3, wA0.w, acc0))));
                acc1 = fmaf(m0, wA1.x, fmaf(m1, wA1.y, fmaf(m2, wA1.z, fmaf(m3, wA1.w, acc1))));
            }
            // ---- patch B: t = (r0.z, r0.w, r1.z, r1.w)
            {
                float s0, c0, sa, ca;
                __sincosf(r0.z, &s0, &c0);
                __sincosf(r0.w + P1, &sa, &ca);
                const float ct2 = __cosf(r1.z);
                const float ct3 = __cosf(r1.w);
                const float m0 = fmaf(K1, c0, -K2 * sa * s0);
                const float m1 = K3 * ca * c0;
                const float m2 = ct2;
                const float m3 = K4 * ct2 * ct3;
                acc0 = fmaf(m0, wB0.x, fmaf(m1, wB0.y, fmaf(m2, wB0.z, fmaf(m3, wB0.w, acc0))));
                acc1 = fmaf(m0, wB1.x, fmaf(m1, wB1.y, fmaf(m2, wB1.z, fmaf(m3, wB1.w, acc1))));
            }
        }
    }

    // warp shuffle reduction (deterministic fixed order)
#pragma unroll
    for (int off = 16; off > 0; off >>= 1) {
        acc0 += __shfl_down_sync(0xFFFFFFFFu, acc0, off);
        acc1 += __shfl_down_sync(0xFFFFFFFFu, acc1, off);
    }
    if ((tid & 31) == 0) warpred[tid >> 5] = make_float2(acc0, acc1);
    __syncthreads();

    if (tid == 0) {
        float l0 = bias[0], l1 = bias[1];
#pragma unroll
        for (int w = 0; w < BLK / 32; w++) {
            l0 += warpred[w].x;
            l1 += warpred[w].y;
        }
        const float m = fmaxf(l0, l1);
        const float lse = m + logf(expf(l0 - m) + expf(l1 - m));
        out[b * 2 + 0] = l0 - lse;
        out[b * 2 + 1] = l1 - lse;
    }
}

extern "C" void kernel_launch(void* const* d_in, const int* in_sizes, int n_in,
                              void* d_out, int out_size)
{
    (void)in_sizes; (void)n_in; (void)out_size;
    const float* x    = (const float*)d_in[0];  // [64,100,100]
    const float* W    = (const float*)d_in[1];  // [2,10000]
    const float* bias = (const float*)d_in[2];  // [2]
    const float* qp   = (const float*)d_in[3];  // [6]

    fused_kernel<<<64, BLK>>>(x, W, bias, qp, (float*)d_out);
}